// round 3
// baseline (speedup 1.0000x reference)
#include <cuda_runtime.h>
#include <cstdint>

#define D 64
#define N_MAX 200000
#define E_MAX 4000000
#define SCAN_T 1024

// ---- scratch (static device globals; no allocation allowed) ----
__device__ int   g_deg[N_MAX];
__device__ int   g_off[N_MAX];
__device__ int   g_cur[N_MAX];
__device__ float g_dinv[N_MAX];
__device__ int2  g_pairs[E_MAX];                 // (src, bitcast(norm))
__device__ float g_bufA[(size_t)N_MAX * D];
__device__ float g_bufB[(size_t)N_MAX * D];
__device__ int   g_bsum[256];
__device__ int   g_bscan[256];

// ---------------- degree / norm ----------------
__global__ void k_zero_deg(int n) {
    int i = blockIdx.x * blockDim.x + threadIdx.x;
    if (i < n) g_deg[i] = 0;
}

__global__ void k_count(const int* __restrict__ dst, int E) {
    int i = blockIdx.x * blockDim.x + threadIdx.x;
    if (i < E) atomicAdd(&g_deg[dst[i]], 1);
}

__global__ void k_dinv(int n) {
    int i = blockIdx.x * blockDim.x + threadIdx.x;
    if (i < n) {
        int d = g_deg[i];
        g_dinv[i] = (d > 0) ? rsqrtf((float)d) : 0.0f;
    }
}

// ---------------- exclusive scan (3 kernels) ----------------
__global__ void k_scanA(int n) {
    __shared__ int s[SCAN_T];
    int t = threadIdx.x;
    int i = blockIdx.x * SCAN_T + t;
    int v = (i < n) ? g_deg[i] : 0;
    s[t] = v;
    __syncthreads();
    for (int d = 1; d < SCAN_T; d <<= 1) {
        int x = (t >= d) ? s[t - d] : 0;
        __syncthreads();
        s[t] += x;
        __syncthreads();
    }
    if (i < n) g_off[i] = s[t] - v;               // exclusive within block
    if (t == SCAN_T - 1) g_bsum[blockIdx.x] = s[t];
}

__global__ void k_scanB(int nb) {
    __shared__ int s[256];
    int t = threadIdx.x;
    int v = (t < nb) ? g_bsum[t] : 0;
    s[t] = v;
    __syncthreads();
    for (int d = 1; d < 256; d <<= 1) {
        int x = (t >= d) ? s[t - d] : 0;
        __syncthreads();
        s[t] += x;
        __syncthreads();
    }
    if (t < nb) g_bscan[t] = s[t] - v;
}

__global__ void k_scanC(int n) {
    int i = blockIdx.x * SCAN_T + threadIdx.x;
    if (i < n) {
        int o = g_off[i] + g_bscan[blockIdx.x];
        g_off[i] = o;
        g_cur[i] = o;
    }
}

// ---------------- CSR fill ----------------
__global__ void k_fill(const int* __restrict__ src,
                       const int* __restrict__ dst, int E) {
    int i = blockIdx.x * blockDim.x + threadIdx.x;
    if (i < E) {
        int s = src[i];
        int t = dst[i];
        int pos = atomicAdd(&g_cur[t], 1);
        float w = g_dinv[s] * g_dinv[t];
        g_pairs[pos] = make_int2(s, __float_as_int(w));
    }
}

// ---------------- init outputs: out0 = emb0, acc = emb0 ----------------
__global__ void k_init(const float4* __restrict__ emb, float4* __restrict__ o0,
                       float4* __restrict__ acc, int n4) {
    int i = blockIdx.x * blockDim.x + threadIdx.x;
    if (i < n4) {
        float4 v = emb[i];
        o0[i] = v;
        acc[i] = v;
    }
}

// ---------------- propagation: one warp per destination node ----------------
// layer 0: in = emb0,  writes g_bufA + acc += sum
// layer 1: in = bufA,  writes g_bufB + acc += sum
// layer 2: in = bufB,  acc = (acc + sum) * 0.25   (final)
__global__ void __launch_bounds__(256) k_prop(const float* __restrict__ emb0,
                                              float* __restrict__ acc,
                                              int layer, int n) {
    int warp = (blockIdx.x * blockDim.x + threadIdx.x) >> 5;
    int lane = threadIdx.x & 31;
    if (warp >= n) return;

    const float* __restrict__ in =
        (layer == 0) ? emb0 : ((layer == 1) ? g_bufA : g_bufB);
    float* __restrict__ outbuf = (layer == 0) ? g_bufA : g_bufB;

    int lo  = g_off[warp];
    int cnt = g_deg[warp];
    int end = lo + cnt;
    int c2  = lane << 1;

    float sx = 0.0f, sy = 0.0f;
    int j = lo;
    // 4-way unroll: 4 independent gather loads in flight per warp
    for (; j + 4 <= end; j += 4) {
        int2 p0 = g_pairs[j + 0];
        int2 p1 = g_pairs[j + 1];
        int2 p2 = g_pairs[j + 2];
        int2 p3 = g_pairs[j + 3];
        float2 v0 = *reinterpret_cast<const float2*>(in + (((size_t)p0.x) << 6) + c2);
        float2 v1 = *reinterpret_cast<const float2*>(in + (((size_t)p1.x) << 6) + c2);
        float2 v2 = *reinterpret_cast<const float2*>(in + (((size_t)p2.x) << 6) + c2);
        float2 v3 = *reinterpret_cast<const float2*>(in + (((size_t)p3.x) << 6) + c2);
        sx += __int_as_float(p0.y) * v0.x;  sy += __int_as_float(p0.y) * v0.y;
        sx += __int_as_float(p1.y) * v1.x;  sy += __int_as_float(p1.y) * v1.y;
        sx += __int_as_float(p2.y) * v2.x;  sy += __int_as_float(p2.y) * v2.y;
        sx += __int_as_float(p3.y) * v3.x;  sy += __int_as_float(p3.y) * v3.y;
    }
    for (; j < end; ++j) {
        int2 p = g_pairs[j];
        float2 v = *reinterpret_cast<const float2*>(in + (((size_t)p.x) << 6) + c2);
        float w = __int_as_float(p.y);
        sx += w * v.x;
        sy += w * v.y;
    }

    size_t o = (((size_t)warp) << 6) + c2;
    if (layer < 2) {
        *reinterpret_cast<float2*>(outbuf + o) = make_float2(sx, sy);
        float2 a = *reinterpret_cast<float2*>(acc + o);
        a.x += sx; a.y += sy;
        *reinterpret_cast<float2*>(acc + o) = a;
    } else {
        float2 a = *reinterpret_cast<float2*>(acc + o);
        a.x = (a.x + sx) * 0.25f;
        a.y = (a.y + sy) * 0.25f;
        *reinterpret_cast<float2*>(acc + o) = a;
    }
}

extern "C" void kernel_launch(void* const* d_in, const int* in_sizes, int n_in,
                              void* d_out, int out_size) {
    const int*   edges = (const int*)d_in[0];       // int32 (JAX x64 disabled demotes int64)
    const float* emb   = (const float*)d_in[1];
    int E = in_sizes[0] / 2;
    int N = in_sizes[1] / D;

    const int* src = edges;
    const int* dst = edges + E;

    float* out0 = (float*)d_out;
    float* acc  = out0 + (size_t)N * D;

    int tb = 256;
    int nbN = (N + tb - 1) / tb;
    int nbE = (E + tb - 1) / tb;
    int NB  = (N + SCAN_T - 1) / SCAN_T;   // 196 blocks for N=200000

    k_zero_deg<<<nbN, tb>>>(N);
    k_count<<<nbE, tb>>>(dst, E);
    k_dinv<<<nbN, tb>>>(N);
    k_scanA<<<NB, SCAN_T>>>(N);
    k_scanB<<<1, 256>>>(NB);
    k_scanC<<<NB, SCAN_T>>>(N);
    k_fill<<<nbE, tb>>>(src, dst, E);

    int n4 = (N * D) / 4;
    k_init<<<(n4 + tb - 1) / tb, tb>>>((const float4*)emb, (float4*)out0,
                                       (float4*)acc, n4);

    int pthreads = N * 32;                  // one warp per node
    int pblocks  = (pthreads + tb - 1) / tb;
    k_prop<<<pblocks, tb>>>(emb, acc, 0, N);
    k_prop<<<pblocks, tb>>>(emb, acc, 1, N);
    k_prop<<<pblocks, tb>>>(emb, acc, 2, N);
}

// round 5
// speedup vs baseline: 1.0431x; 1.0431x over previous
#include <cuda_runtime.h>
#include <cuda_fp16.h>
#include <cstdint>

#define D 64
#define N_MAX 200000
#define E_MAX 4000000
#define SCAN_T 1024

// ---- scratch (static device globals; no allocation allowed) ----
__device__ int     g_deg[N_MAX];
__device__ int     g_off[N_MAX];
__device__ int     g_cur[N_MAX];
__device__ float   g_dinv[N_MAX];
__device__ int2    g_pairs[E_MAX];                    // (src, bitcast(norm))
__device__ __half2 g_h0[(size_t)N_MAX * 32];          // emb0 in fp16
__device__ __half2 g_h1[(size_t)N_MAX * 32];          // layer-1 out in fp16
__device__ __half2 g_h2[(size_t)N_MAX * 32];          // layer-2 out in fp16
__device__ int     g_bsum[256];
__device__ int     g_bscan[256];

// ---------------- degree / norm ----------------
__global__ void k_zero_deg(int n) {
    int i = blockIdx.x * blockDim.x + threadIdx.x;
    if (i < n) g_deg[i] = 0;
}

__global__ void k_count(const int* __restrict__ dst, int E) {
    int i = blockIdx.x * blockDim.x + threadIdx.x;
    if (i < E) atomicAdd(&g_deg[dst[i]], 1);
}

__global__ void k_dinv(int n) {
    int i = blockIdx.x * blockDim.x + threadIdx.x;
    if (i < n) {
        int d = g_deg[i];
        g_dinv[i] = (d > 0) ? rsqrtf((float)d) : 0.0f;
    }
}

// ---------------- exclusive scan (3 kernels) ----------------
__global__ void k_scanA(int n) {
    __shared__ int s[SCAN_T];
    int t = threadIdx.x;
    int i = blockIdx.x * SCAN_T + t;
    int v = (i < n) ? g_deg[i] : 0;
    s[t] = v;
    __syncthreads();
    for (int d = 1; d < SCAN_T; d <<= 1) {
        int x = (t >= d) ? s[t - d] : 0;
        __syncthreads();
        s[t] += x;
        __syncthreads();
    }
    if (i < n) g_off[i] = s[t] - v;
    if (t == SCAN_T - 1) g_bsum[blockIdx.x] = s[t];
}

__global__ void k_scanB(int nb) {
    __shared__ int s[256];
    int t = threadIdx.x;
    int v = (t < nb) ? g_bsum[t] : 0;
    s[t] = v;
    __syncthreads();
    for (int d = 1; d < 256; d <<= 1) {
        int x = (t >= d) ? s[t - d] : 0;
        __syncthreads();
        s[t] += x;
        __syncthreads();
    }
    if (t < nb) g_bscan[t] = s[t] - v;
}

__global__ void k_scanC(int n) {
    int i = blockIdx.x * SCAN_T + threadIdx.x;
    if (i < n) {
        int o = g_off[i] + g_bscan[blockIdx.x];
        g_off[i] = o;
        g_cur[i] = o;
    }
}

// ---------------- CSR fill ----------------
__global__ void k_fill(const int* __restrict__ src,
                       const int* __restrict__ dst, int E) {
    int i = blockIdx.x * blockDim.x + threadIdx.x;
    if (i < E) {
        int s = src[i];
        int t = dst[i];
        int pos = atomicAdd(&g_cur[t], 1);
        float w = g_dinv[s] * g_dinv[t];
        g_pairs[pos] = make_int2(s, __float_as_int(w));
    }
}

// ---------------- init: out0 = emb0, acc = emb0, g_h0 = fp16(emb0) ----------------
__global__ void k_init(const float4* __restrict__ emb, float4* __restrict__ o0,
                       float4* __restrict__ acc, int n4) {
    int i = blockIdx.x * blockDim.x + threadIdx.x;
    if (i < n4) {
        float4 v = emb[i];
        o0[i] = v;
        acc[i] = v;
        g_h0[2 * i]     = __float22half2_rn(make_float2(v.x, v.y));
        g_h0[2 * i + 1] = __float22half2_rn(make_float2(v.z, v.w));
    }
}

// ---------------- propagation: one warp per destination node ----------------
// layer 0: in = g_h0, out = g_h1, acc += sum          (sum in fp32)
// layer 1: in = g_h1, out = g_h2, acc += sum
// layer 2: in = g_h2, acc = (acc + sum) * 0.25        (final)
__global__ void __launch_bounds__(256) k_prop(float* __restrict__ acc,
                                              int layer, int n) {
    int warp = (blockIdx.x * blockDim.x + threadIdx.x) >> 5;
    int lane = threadIdx.x & 31;
    if (warp >= n) return;

    const __half2* __restrict__ in =
        (layer == 0) ? g_h0 : ((layer == 1) ? g_h1 : g_h2);
    __half2* __restrict__ outbuf = (layer == 0) ? g_h1 : g_h2;

    int lo  = g_off[warp];
    int end = lo + g_deg[warp];

    float sx = 0.0f, sy = 0.0f;
    int j = lo;
    // 4-way unroll: 4 independent 4B gather loads in flight per lane
    for (; j + 4 <= end; j += 4) {
        int2 p0 = g_pairs[j + 0];
        int2 p1 = g_pairs[j + 1];
        int2 p2 = g_pairs[j + 2];
        int2 p3 = g_pairs[j + 3];
        __half2 h0 = in[(((size_t)p0.x) << 5) + lane];
        __half2 h1 = in[(((size_t)p1.x) << 5) + lane];
        __half2 h2 = in[(((size_t)p2.x) << 5) + lane];
        __half2 h3 = in[(((size_t)p3.x) << 5) + lane];
        float2 v0 = __half22float2(h0);
        float2 v1 = __half22float2(h1);
        float2 v2 = __half22float2(h2);
        float2 v3 = __half22float2(h3);
        float w0 = __int_as_float(p0.y), w1 = __int_as_float(p1.y);
        float w2 = __int_as_float(p2.y), w3 = __int_as_float(p3.y);
        sx = fmaf(w0, v0.x, sx);  sy = fmaf(w0, v0.y, sy);
        sx = fmaf(w1, v1.x, sx);  sy = fmaf(w1, v1.y, sy);
        sx = fmaf(w2, v2.x, sx);  sy = fmaf(w2, v2.y, sy);
        sx = fmaf(w3, v3.x, sx);  sy = fmaf(w3, v3.y, sy);
    }
    for (; j < end; ++j) {
        int2 p = g_pairs[j];
        float2 v = __half22float2(in[(((size_t)p.x) << 5) + lane]);
        float w = __int_as_float(p.y);
        sx = fmaf(w, v.x, sx);
        sy = fmaf(w, v.y, sy);
    }

    size_t o = (((size_t)warp) << 6) + (lane << 1);
    if (layer < 2) {
        outbuf[(((size_t)warp) << 5) + lane] = __float22half2_rn(make_float2(sx, sy));
        float2 a = *reinterpret_cast<float2*>(acc + o);
        a.x += sx; a.y += sy;
        *reinterpret_cast<float2*>(acc + o) = a;
    } else {
        float2 a = *reinterpret_cast<float2*>(acc + o);
        a.x = (a.x + sx) * 0.25f;
        a.y = (a.y + sy) * 0.25f;
        *reinterpret_cast<float2*>(acc + o) = a;
    }
}

extern "C" void kernel_launch(void* const* d_in, const int* in_sizes, int n_in,
                              void* d_out, int out_size) {
    const int*   edges = (const int*)d_in[0];       // int32
    const float* emb   = (const float*)d_in[1];
    int E = in_sizes[0] / 2;
    int N = in_sizes[1] / D;

    const int* src = edges;
    const int* dst = edges + E;

    float* out0 = (float*)d_out;
    float* acc  = out0 + (size_t)N * D;

    int tb = 256;
    int nbN = (N + tb - 1) / tb;
    int nbE = (E + tb - 1) / tb;
    int NB  = (N + SCAN_T - 1) / SCAN_T;

    k_zero_deg<<<nbN, tb>>>(N);
    k_count<<<nbE, tb>>>(dst, E);
    k_dinv<<<nbN, tb>>>(N);
    k_scanA<<<NB, SCAN_T>>>(N);
    k_scanB<<<1, 256>>>(NB);
    k_scanC<<<NB, SCAN_T>>>(N);
    k_fill<<<nbE, tb>>>(src, dst, E);

    int n4 = (N * D) / 4;
    k_init<<<(n4 + tb - 1) / tb, tb>>>((const float4*)emb, (float4*)out0,
                                       (float4*)acc, n4);

    int pthreads = N * 32;                  // one warp per node
    int pblocks  = (pthreads + tb - 1) / tb;
    k_prop<<<pblocks, tb>>>(acc, 0, N);
    k_prop<<<pblocks, tb>>>(acc, 1, N);
    k_prop<<<pblocks, tb>>>(acc, 2, N);
}

// round 7
// speedup vs baseline: 1.0528x; 1.0092x over previous
#include <cuda_runtime.h>
#include <cuda_fp16.h>
#include <cstdint>

#define D 64
#define N_MAX 200000
#define E_MAX 4000000
#define SCAN_T 1024

// ---- scratch (static device globals; no allocation allowed) ----
__device__ int     g_deg[N_MAX];
__device__ int     g_off[N_MAX];
__device__ int     g_cur[N_MAX];
__device__ float   g_dinv[N_MAX];
__device__ __align__(16) int2 g_pairs[E_MAX];         // (src, bitcast(norm))
__device__ __half2 g_h0[(size_t)N_MAX * 32];          // emb0 in fp16
__device__ __half2 g_h1[(size_t)N_MAX * 32];          // layer-1 out in fp16
__device__ __half2 g_h2[(size_t)N_MAX * 32];          // layer-2 out in fp16
__device__ int     g_bsum[256];
__device__ int     g_bscan[256];

// ---------------- degree / norm ----------------
__global__ void k_zero_deg(int n) {
    int i = blockIdx.x * blockDim.x + threadIdx.x;
    if (i < n) g_deg[i] = 0;
}

__global__ void k_count(const int* __restrict__ dst, int E) {
    int i = blockIdx.x * blockDim.x + threadIdx.x;
    if (i < E) atomicAdd(&g_deg[dst[i]], 1);
}

__global__ void k_dinv(int n) {
    int i = blockIdx.x * blockDim.x + threadIdx.x;
    if (i < n) {
        int d = g_deg[i];
        g_dinv[i] = (d > 0) ? rsqrtf((float)d) : 0.0f;
    }
}

// ---------------- exclusive scan (3 kernels) ----------------
__global__ void k_scanA(int n) {
    __shared__ int s[SCAN_T];
    int t = threadIdx.x;
    int i = blockIdx.x * SCAN_T + t;
    int v = (i < n) ? g_deg[i] : 0;
    s[t] = v;
    __syncthreads();
    for (int d = 1; d < SCAN_T; d <<= 1) {
        int x = (t >= d) ? s[t - d] : 0;
        __syncthreads();
        s[t] += x;
        __syncthreads();
    }
    if (i < n) g_off[i] = s[t] - v;
    if (t == SCAN_T - 1) g_bsum[blockIdx.x] = s[t];
}

__global__ void k_scanB(int nb) {
    __shared__ int s[256];
    int t = threadIdx.x;
    int v = (t < nb) ? g_bsum[t] : 0;
    s[t] = v;
    __syncthreads();
    for (int d = 1; d < 256; d <<= 1) {
        int x = (t >= d) ? s[t - d] : 0;
        __syncthreads();
        s[t] += x;
        __syncthreads();
    }
    if (t < nb) g_bscan[t] = s[t] - v;
}

__global__ void k_scanC(int n) {
    int i = blockIdx.x * SCAN_T + threadIdx.x;
    if (i < n) {
        int o = g_off[i] + g_bscan[blockIdx.x];
        g_off[i] = o;
        g_cur[i] = o;
    }
}

// ---------------- CSR fill ----------------
__global__ void k_fill(const int* __restrict__ src,
                       const int* __restrict__ dst, int E) {
    int i = blockIdx.x * blockDim.x + threadIdx.x;
    if (i < E) {
        int s = src[i];
        int t = dst[i];
        int pos = atomicAdd(&g_cur[t], 1);
        float w = g_dinv[s] * g_dinv[t];
        g_pairs[pos] = make_int2(s, __float_as_int(w));
    }
}

// ---------------- init: out0 = emb0, g_h0 = fp16(emb0) ----------------
__global__ void k_init(const float4* __restrict__ emb, float4* __restrict__ o0,
                       int n4) {
    int i = blockIdx.x * blockDim.x + threadIdx.x;
    if (i < n4) {
        float4 v = emb[i];
        o0[i] = v;
        g_h0[2 * i]     = __float22half2_rn(make_float2(v.x, v.y));
        g_h0[2 * i + 1] = __float22half2_rn(make_float2(v.z, v.w));
    }
}

// ---------------- gather-sum over one node's edge list ----------------
// 8 independent gather loads + 4 int4 pair loads in flight per unroll block.
__device__ __forceinline__ float2 gather_sum(const __half2* __restrict__ in,
                                             int lo, int end, int lane) {
    float sx = 0.0f, sy = 0.0f;
    int j = lo;
    if ((j & 1) && j < end) {                 // peel to even index for int4 pair loads
        int2 p = g_pairs[j];
        float2 v = __half22float2(in[(((size_t)p.x) << 5) + lane]);
        float w = __int_as_float(p.y);
        sx = fmaf(w, v.x, sx); sy = fmaf(w, v.y, sy);
        ++j;
    }
    const int4* __restrict__ p4 = reinterpret_cast<const int4*>(g_pairs);
    for (; j + 8 <= end; j += 8) {
        int4 a = p4[(j >> 1) + 0];
        int4 b = p4[(j >> 1) + 1];
        int4 c = p4[(j >> 1) + 2];
        int4 d = p4[(j >> 1) + 3];
        __half2 h0 = in[(((size_t)a.x) << 5) + lane];
        __half2 h1 = in[(((size_t)a.z) << 5) + lane];
        __half2 h2 = in[(((size_t)b.x) << 5) + lane];
        __half2 h3 = in[(((size_t)b.z) << 5) + lane];
        __half2 h4 = in[(((size_t)c.x) << 5) + lane];
        __half2 h5 = in[(((size_t)c.z) << 5) + lane];
        __half2 h6 = in[(((size_t)d.x) << 5) + lane];
        __half2 h7 = in[(((size_t)d.z) << 5) + lane];
        float2 v0 = __half22float2(h0), v1 = __half22float2(h1);
        float2 v2 = __half22float2(h2), v3 = __half22float2(h3);
        float2 v4 = __half22float2(h4), v5 = __half22float2(h5);
        float2 v6 = __half22float2(h6), v7 = __half22float2(h7);
        float w0 = __int_as_float(a.y), w1 = __int_as_float(a.w);
        float w2 = __int_as_float(b.y), w3 = __int_as_float(b.w);
        float w4 = __int_as_float(c.y), w5 = __int_as_float(c.w);
        float w6 = __int_as_float(d.y), w7 = __int_as_float(d.w);
        sx = fmaf(w0, v0.x, sx);  sy = fmaf(w0, v0.y, sy);
        sx = fmaf(w1, v1.x, sx);  sy = fmaf(w1, v1.y, sy);
        sx = fmaf(w2, v2.x, sx);  sy = fmaf(w2, v2.y, sy);
        sx = fmaf(w3, v3.x, sx);  sy = fmaf(w3, v3.y, sy);
        sx = fmaf(w4, v4.x, sx);  sy = fmaf(w4, v4.y, sy);
        sx = fmaf(w5, v5.x, sx);  sy = fmaf(w5, v5.y, sy);
        sx = fmaf(w6, v6.x, sx);  sy = fmaf(w6, v6.y, sy);
        sx = fmaf(w7, v7.x, sx);  sy = fmaf(w7, v7.y, sy);
    }
    for (; j + 2 <= end; j += 2) {
        int4 a = p4[j >> 1];
        __half2 h0 = in[(((size_t)a.x) << 5) + lane];
        __half2 h1 = in[(((size_t)a.z) << 5) + lane];
        float2 v0 = __half22float2(h0), v1 = __half22float2(h1);
        float w0 = __int_as_float(a.y), w1 = __int_as_float(a.w);
        sx = fmaf(w0, v0.x, sx);  sy = fmaf(w0, v0.y, sy);
        sx = fmaf(w1, v1.x, sx);  sy = fmaf(w1, v1.y, sy);
    }
    if (j < end) {
        int2 p = g_pairs[j];
        float2 v = __half22float2(in[(((size_t)p.x) << 5) + lane]);
        float w = __int_as_float(p.y);
        sx = fmaf(w, v.x, sx);  sy = fmaf(w, v.y, sy);
    }
    return make_float2(sx, sy);
}

// layers 0/1: gather from in, write fp16 layer output only (no acc traffic)
__global__ void __launch_bounds__(256) k_prop(const __half2* __restrict__ in,
                                              __half2* __restrict__ out, int n) {
    int warp = (blockIdx.x * blockDim.x + threadIdx.x) >> 5;
    int lane = threadIdx.x & 31;
    if (warp >= n) return;
    int lo = g_off[warp];
    float2 s = gather_sum(in, lo, lo + g_deg[warp], lane);
    out[(((size_t)warp) << 5) + lane] = __float22half2_rn(s);
}

// final layer: out = (emb0 + h1 + h2 + gather(h2)) * 0.25
__global__ void __launch_bounds__(256) k_prop_final(const float* __restrict__ emb0,
                                                    float* __restrict__ outp, int n) {
    int warp = (blockIdx.x * blockDim.x + threadIdx.x) >> 5;
    int lane = threadIdx.x & 31;
    if (warp >= n) return;
    int lo = g_off[warp];
    float2 s = gather_sum(g_h2, lo, lo + g_deg[warp], lane);

    size_t o32 = (((size_t)warp) << 5) + lane;
    float2 e0 = *reinterpret_cast<const float2*>(emb0 + (o32 << 1));
    float2 a1 = __half22float2(g_h1[o32]);
    float2 a2 = __half22float2(g_h2[o32]);
    float2 r;
    r.x = (e0.x + a1.x + a2.x + s.x) * 0.25f;
    r.y = (e0.y + a1.y + a2.y + s.y) * 0.25f;
    *reinterpret_cast<float2*>(outp + (o32 << 1)) = r;
}

extern "C" void kernel_launch(void* const* d_in, const int* in_sizes, int n_in,
                              void* d_out, int out_size) {
    const int*   edges = (const int*)d_in[0];       // int32
    const float* emb   = (const float*)d_in[1];
    int E = in_sizes[0] / 2;
    int N = in_sizes[1] / D;

    const int* src = edges;
    const int* dst = edges + E;

    float* out0 = (float*)d_out;
    float* outp = out0 + (size_t)N * D;

    int tb = 256;
    int nbN = (N + tb - 1) / tb;
    int nbE = (E + tb - 1) / tb;
    int NB  = (N + SCAN_T - 1) / SCAN_T;

    k_zero_deg<<<nbN, tb>>>(N);
    k_count<<<nbE, tb>>>(dst, E);
    k_dinv<<<nbN, tb>>>(N);
    k_scanA<<<NB, SCAN_T>>>(N);
    k_scanB<<<1, 256>>>(NB);
    k_scanC<<<NB, SCAN_T>>>(N);
    k_fill<<<nbE, tb>>>(src, dst, E);

    int n4 = (N * D) / 4;
    k_init<<<(n4 + tb - 1) / tb, tb>>>((const float4*)emb, (float4*)out0, n4);

    int pthreads = N * 32;                  // one warp per node
    int pblocks  = (pthreads + tb - 1) / tb;
    // expose __device__ globals as kernel args to let ptxas use __restrict__
    __half2 *h0p, *h1p, *h2p;
    cudaGetSymbolAddress((void**)&h0p, g_h0);
    cudaGetSymbolAddress((void**)&h1p, g_h1);
    cudaGetSymbolAddress((void**)&h2p, g_h2);
    k_prop<<<pblocks, tb>>>(h0p, h1p, N);
    k_prop<<<pblocks, tb>>>(h1p, h2p, N);
    k_prop_final<<<pblocks, tb>>>(emb, outp, N);
}

// round 8
// speedup vs baseline: 1.0910x; 1.0363x over previous
#include <cuda_runtime.h>
#include <cuda_fp16.h>
#include <cstdint>

#define D 64
#define N_MAX 200000
#define E_MAX 4000000
#define SCAN_T 1024

// ---- scratch (static device globals; zero-initialized at module load) ----
__device__ int     g_deg[N_MAX];       // zeroed at load; re-zeroed by k_prop_final each call
__device__ int     g_off[N_MAX];
__device__ int     g_cur[N_MAX];
__device__ float   g_dinv[N_MAX];
__device__ __align__(16) int2 g_pairs[E_MAX];   // (src, bitcast(norm))
__device__ __half2 g_h0[(size_t)N_MAX * 32];    // emb0 in fp16
__device__ __half2 g_h1[(size_t)N_MAX * 32];    // layer-1 out
__device__ __half2 g_h2[(size_t)N_MAX * 32];    // layer-2 out
__device__ int     g_bsum[256];

// ---------------- degree count (g_deg must be 0 on entry) ----------------
__global__ void k_count(const int* __restrict__ dst, int E) {
    int i = blockIdx.x * blockDim.x + threadIdx.x;
    if (i < E) atomicAdd(&g_deg[dst[i]], 1);
}

// ---------------- block-local exclusive scan + dinv fused ----------------
__global__ void k_scanA(int n) {
    __shared__ int s[SCAN_T];
    int t = threadIdx.x;
    int i = blockIdx.x * SCAN_T + t;
    int v = (i < n) ? g_deg[i] : 0;
    s[t] = v;
    __syncthreads();
    for (int d = 1; d < SCAN_T; d <<= 1) {
        int x = (t >= d) ? s[t - d] : 0;
        __syncthreads();
        s[t] += x;
        __syncthreads();
    }
    if (i < n) {
        g_off[i]  = s[t] - v;                       // exclusive within block
        g_dinv[i] = (v > 0) ? rsqrtf((float)v) : 0.0f;
    }
    if (t == SCAN_T - 1) g_bsum[blockIdx.x] = s[t];
}

// ---------------- merged scanB+scanC: every block scans the block sums ----------------
__global__ void k_scanBC(int n, int nb) {
    __shared__ int s[256];
    int t = threadIdx.x;
    if (t < 256) s[t] = (t < nb) ? g_bsum[t] : 0;
    __syncthreads();
    for (int d = 1; d < 256; d <<= 1) {
        int x = (t < 256 && t >= d) ? s[t - d] : 0;
        __syncthreads();
        if (t < 256) s[t] += x;
        __syncthreads();
    }
    int excl = s[blockIdx.x] - g_bsum[blockIdx.x];  // exclusive prefix of this block
    int i = blockIdx.x * SCAN_T + t;
    if (i < n) {
        int o = g_off[i] + excl;
        g_off[i] = o;
        g_cur[i] = o;
    }
}

// ---------------- CSR fill ----------------
__global__ void k_fill(const int* __restrict__ src,
                       const int* __restrict__ dst, int E) {
    int i = blockIdx.x * blockDim.x + threadIdx.x;
    if (i < E) {
        int s = src[i];
        int t = dst[i];
        int pos = atomicAdd(&g_cur[t], 1);
        float w = g_dinv[s] * g_dinv[t];
        g_pairs[pos] = make_int2(s, __float_as_int(w));
    }
}

// ---------------- init: out0 = emb0, g_h0 = fp16(emb0) ----------------
__global__ void k_init(const float4* __restrict__ emb, float4* __restrict__ o0,
                       int n4) {
    int i = blockIdx.x * blockDim.x + threadIdx.x;
    if (i < n4) {
        float4 v = emb[i];
        o0[i] = v;
        g_h0[2 * i]     = __float22half2_rn(make_float2(v.x, v.y));
        g_h0[2 * i + 1] = __float22half2_rn(make_float2(v.z, v.w));
    }
}

// ---------------- gather-sum: warp per node, 2 edges/iter, half-warp per edge ----------------
// Each lane loads 8B (uint2 = 2 half2 = cols sub*4..sub*4+3) of its side's edge row.
// Side 0 = even edges, side 1 = odd edges; cross-side reduction at the end via SHFL.BFLY(16).
__device__ __forceinline__ float4 gather_sum2(const __half2* __restrict__ in_,
                                              int lo, int end, int side, int sub) {
    const uint2* __restrict__ in2 = reinterpret_cast<const uint2*>(in_);
    float ax = 0.f, ay = 0.f, az = 0.f, aw = 0.f;
    int j = lo;

    // peel to even index (side 0 handles it, side 1 idles)
    if ((j & 1) && j < end) {
        if (side == 0) {
            int2 p = g_pairs[j];
            uint2 r = in2[(((size_t)p.x) << 4) + sub];
            float2 fa = __half22float2(*reinterpret_cast<__half2*>(&r.x));
            float2 fb = __half22float2(*reinterpret_cast<__half2*>(&r.y));
            float w = __int_as_float(p.y);
            ax = fmaf(w, fa.x, ax); ay = fmaf(w, fa.y, ay);
            az = fmaf(w, fb.x, az); aw = fmaf(w, fb.y, aw);
        }
        ++j;
    }
    const int4* __restrict__ p4 = reinterpret_cast<const int4*>(g_pairs);

    // main loop: 8 edges per trip, 4 gather LDGs per lane in flight
    for (; j + 8 <= end; j += 8) {
        int4 a = p4[(j >> 1) + 0];
        int4 b = p4[(j >> 1) + 1];
        int4 c = p4[(j >> 1) + 2];
        int4 d = p4[(j >> 1) + 3];
        int  s0 = side ? a.z : a.x;  float w0 = __int_as_float(side ? a.w : a.y);
        int  s1 = side ? b.z : b.x;  float w1 = __int_as_float(side ? b.w : b.y);
        int  s2 = side ? c.z : c.x;  float w2 = __int_as_float(side ? c.w : c.y);
        int  s3 = side ? d.z : d.x;  float w3 = __int_as_float(side ? d.w : d.y);
        uint2 r0 = in2[(((size_t)s0) << 4) + sub];
        uint2 r1 = in2[(((size_t)s1) << 4) + sub];
        uint2 r2 = in2[(((size_t)s2) << 4) + sub];
        uint2 r3 = in2[(((size_t)s3) << 4) + sub];
        float2 f0a = __half22float2(*reinterpret_cast<__half2*>(&r0.x));
        float2 f0b = __half22float2(*reinterpret_cast<__half2*>(&r0.y));
        float2 f1a = __half22float2(*reinterpret_cast<__half2*>(&r1.x));
        float2 f1b = __half22float2(*reinterpret_cast<__half2*>(&r1.y));
        float2 f2a = __half22float2(*reinterpret_cast<__half2*>(&r2.x));
        float2 f2b = __half22float2(*reinterpret_cast<__half2*>(&r2.y));
        float2 f3a = __half22float2(*reinterpret_cast<__half2*>(&r3.x));
        float2 f3b = __half22float2(*reinterpret_cast<__half2*>(&r3.y));
        ax = fmaf(w0, f0a.x, ax); ay = fmaf(w0, f0a.y, ay);
        az = fmaf(w0, f0b.x, az); aw = fmaf(w0, f0b.y, aw);
        ax = fmaf(w1, f1a.x, ax); ay = fmaf(w1, f1a.y, ay);
        az = fmaf(w1, f1b.x, az); aw = fmaf(w1, f1b.y, aw);
        ax = fmaf(w2, f2a.x, ax); ay = fmaf(w2, f2a.y, ay);
        az = fmaf(w2, f2b.x, az); aw = fmaf(w2, f2b.y, aw);
        ax = fmaf(w3, f3a.x, ax); ay = fmaf(w3, f3a.y, ay);
        az = fmaf(w3, f3b.x, az); aw = fmaf(w3, f3b.y, aw);
    }
    // pair tail (2 edges at a time)
    for (; j + 2 <= end; j += 2) {
        int4 a = p4[j >> 1];
        int  s0 = side ? a.z : a.x;  float w0 = __int_as_float(side ? a.w : a.y);
        uint2 r0 = in2[(((size_t)s0) << 4) + sub];
        float2 fa = __half22float2(*reinterpret_cast<__half2*>(&r0.x));
        float2 fb = __half22float2(*reinterpret_cast<__half2*>(&r0.y));
        ax = fmaf(w0, fa.x, ax); ay = fmaf(w0, fa.y, ay);
        az = fmaf(w0, fb.x, az); aw = fmaf(w0, fb.y, aw);
    }
    // last single edge
    if (j < end && side == 0) {
        int2 p = g_pairs[j];
        uint2 r = in2[(((size_t)p.x) << 4) + sub];
        float2 fa = __half22float2(*reinterpret_cast<__half2*>(&r.x));
        float2 fb = __half22float2(*reinterpret_cast<__half2*>(&r.y));
        float w = __int_as_float(p.y);
        ax = fmaf(w, fa.x, ax); ay = fmaf(w, fa.y, ay);
        az = fmaf(w, fb.x, az); aw = fmaf(w, fb.y, aw);
    }
    // combine the two sides
    ax += __shfl_xor_sync(0xffffffffu, ax, 16);
    ay += __shfl_xor_sync(0xffffffffu, ay, 16);
    az += __shfl_xor_sync(0xffffffffu, az, 16);
    aw += __shfl_xor_sync(0xffffffffu, aw, 16);
    return make_float4(ax, ay, az, aw);
}

// layers 0/1: gather from in, write fp16 layer output
__global__ void __launch_bounds__(256) k_prop(const __half2* __restrict__ in,
                                              __half2* __restrict__ out, int n) {
    int warp = (blockIdx.x * blockDim.x + threadIdx.x) >> 5;
    int lane = threadIdx.x & 31;
    if (warp >= n) return;
    int side = lane >> 4, sub = lane & 15;
    int lo = g_off[warp];
    float4 s = gather_sum2(in, lo, lo + g_deg[warp], side, sub);
    if (side == 0) {
        __half2 oa = __float22half2_rn(make_float2(s.x, s.y));
        __half2 ob = __float22half2_rn(make_float2(s.z, s.w));
        uint2 o;
        o.x = *reinterpret_cast<unsigned*>(&oa);
        o.y = *reinterpret_cast<unsigned*>(&ob);
        reinterpret_cast<uint2*>(out)[(((size_t)warp) << 4) + sub] = o;
    }
}

// final layer: out = (emb0 + h1 + h2 + gather(h2)) * 0.25; then re-zero g_deg
__global__ void __launch_bounds__(256) k_prop_final(const float* __restrict__ emb0,
                                                    float* __restrict__ outp, int n) {
    int warp = (blockIdx.x * blockDim.x + threadIdx.x) >> 5;
    int lane = threadIdx.x & 31;
    if (warp >= n) return;
    int side = lane >> 4, sub = lane & 15;
    int lo = g_off[warp];
    float4 s = gather_sum2(g_h2, lo, lo + g_deg[warp], side, sub);

    if (side == 0) {
        size_t ro = (((size_t)warp) << 4) + sub;
        float4 e0 = reinterpret_cast<const float4*>(emb0)[ro];
        uint2 r1 = reinterpret_cast<const uint2*>(g_h1)[ro];
        uint2 r2 = reinterpret_cast<const uint2*>(g_h2)[ro];
        float2 a1a = __half22float2(*reinterpret_cast<__half2*>(&r1.x));
        float2 a1b = __half22float2(*reinterpret_cast<__half2*>(&r1.y));
        float2 a2a = __half22float2(*reinterpret_cast<__half2*>(&r2.x));
        float2 a2b = __half22float2(*reinterpret_cast<__half2*>(&r2.y));
        float4 r;
        r.x = (e0.x + a1a.x + a2a.x + s.x) * 0.25f;
        r.y = (e0.y + a1a.y + a2a.y + s.y) * 0.25f;
        r.z = (e0.z + a1b.x + a2b.x + s.z) * 0.25f;
        r.w = (e0.w + a1b.y + a2b.y + s.w) * 0.25f;
        reinterpret_cast<float4*>(outp)[ro] = r;
    }
    if (lane == 0) g_deg[warp] = 0;   // restore invariant for next call (deg already read)
}

extern "C" void kernel_launch(void* const* d_in, const int* in_sizes, int n_in,
                              void* d_out, int out_size) {
    const int*   edges = (const int*)d_in[0];       // int32
    const float* emb   = (const float*)d_in[1];
    int E = in_sizes[0] / 2;
    int N = in_sizes[1] / D;

    const int* src = edges;
    const int* dst = edges + E;

    float* out0 = (float*)d_out;
    float* outp = out0 + (size_t)N * D;

    int tb = 256;
    int nbE = (E + tb - 1) / tb;
    int NB  = (N + SCAN_T - 1) / SCAN_T;

    k_count<<<nbE, tb>>>(dst, E);                   // launch 0
    k_scanA<<<NB, SCAN_T>>>(N);                     // launch 1 (scan + dinv)
    k_scanBC<<<NB, SCAN_T>>>(N, NB);                // launch 2
    k_fill<<<nbE, tb>>>(src, dst, E);               // launch 3

    int n4 = (N * D) / 4;
    k_init<<<(n4 + tb - 1) / tb, tb>>>((const float4*)emb, (float4*)out0, n4);  // 4

    __half2 *h0p, *h1p, *h2p;
    cudaGetSymbolAddress((void**)&h0p, g_h0);
    cudaGetSymbolAddress((void**)&h1p, g_h1);
    cudaGetSymbolAddress((void**)&h2p, g_h2);

    int pthreads = N * 32;                          // one warp per node
    int pblocks  = (pthreads + tb - 1) / tb;
    k_prop<<<pblocks, tb>>>(h0p, h1p, N);           // launch 5
    k_prop<<<pblocks, tb>>>(h1p, h2p, N);           // launch 6
    k_prop_final<<<pblocks, tb>>>(emb, outp, N);    // launch 7
}

// round 10
// speedup vs baseline: 1.2443x; 1.1405x over previous
#include <cuda_runtime.h>
#include <cuda_fp16.h>
#include <cstdint>

#define D 64
#define N_MAX 200000
#define E_MAX 4000000
#define SCAN_T 1024

// ---- scratch (static device globals; zero-initialized at module load) ----
__device__ int     g_deg[N_MAX];       // zeroed at load; re-zeroed by k_prop_final each call
__device__ int     g_off[N_MAX];
__device__ int     g_cur[N_MAX];
__device__ float   g_dinv[N_MAX];
__device__ __align__(16) int g_src[E_MAX];      // CSR adjacency: src only (no weight!)
__device__ __half2 g_s0[(size_t)N_MAX * 32];    // s0 = dinv ⊙ emb0   (fp16, pre-scaled)
__device__ __half2 g_s1[(size_t)N_MAX * 32];    // s1 = dinv ⊙ e1
__device__ __half2 g_s2[(size_t)N_MAX * 32];    // s2 = dinv ⊙ e2
__device__ int     g_bsum[256];

// ---------------- degree count (g_deg must be 0 on entry) ----------------
__global__ void k_count(const int* __restrict__ dst, int E) {
    int i = blockIdx.x * blockDim.x + threadIdx.x;
    if (i < E) atomicAdd(&g_deg[dst[i]], 1);
}

// ---------------- block-local exclusive scan + dinv fused ----------------
__global__ void k_scanA(int n) {
    __shared__ int s[SCAN_T];
    int t = threadIdx.x;
    int i = blockIdx.x * SCAN_T + t;
    int v = (i < n) ? g_deg[i] : 0;
    s[t] = v;
    __syncthreads();
    for (int d = 1; d < SCAN_T; d <<= 1) {
        int x = (t >= d) ? s[t - d] : 0;
        __syncthreads();
        s[t] += x;
        __syncthreads();
    }
    if (i < n) {
        g_off[i]  = s[t] - v;
        g_dinv[i] = (v > 0) ? rsqrtf((float)v) : 0.0f;
    }
    if (t == SCAN_T - 1) g_bsum[blockIdx.x] = s[t];
}

// ---------------- merged scanB+scanC: every block scans the block sums ----------------
__global__ void k_scanBC(int n, int nb) {
    __shared__ int s[256];
    int t = threadIdx.x;
    if (t < 256) s[t] = (t < nb) ? g_bsum[t] : 0;
    __syncthreads();
    for (int d = 1; d < 256; d <<= 1) {
        int x = (t < 256 && t >= d) ? s[t - d] : 0;
        __syncthreads();
        if (t < 256) s[t] += x;
        __syncthreads();
    }
    int excl = s[blockIdx.x] - g_bsum[blockIdx.x];
    int i = blockIdx.x * SCAN_T + t;
    if (i < n) {
        int o = g_off[i] + excl;
        g_off[i] = o;
        g_cur[i] = o;
    }
}

// ---------------- CSR fill: src index only, no dinv reads ----------------
__global__ void k_fill(const int* __restrict__ src,
                       const int* __restrict__ dst, int E) {
    int i = blockIdx.x * blockDim.x + threadIdx.x;
    if (i < E) {
        int pos = atomicAdd(&g_cur[dst[i]], 1);
        g_src[pos] = src[i];
    }
}

// ---------------- init: out0 = emb0, g_s0 = fp16(dinv ⊙ emb0) ----------------
__global__ void k_init(const float4* __restrict__ emb, float4* __restrict__ o0,
                       int n4) {
    int i = blockIdx.x * blockDim.x + threadIdx.x;
    if (i < n4) {
        float4 v = emb[i];
        o0[i] = v;
        float dv = g_dinv[i >> 4];                 // 16 float4 per node row
        g_s0[2 * i]     = __float22half2_rn(make_float2(v.x * dv, v.y * dv));
        g_s0[2 * i + 1] = __float22half2_rn(make_float2(v.z * dv, v.w * dv));
    }
}

// ---------------- gather-sum: warp per node, half-warp per edge, plain adds ----------------
#define ACC(r) do { \
    float2 _fa = __half22float2(*reinterpret_cast<__half2*>(&(r).x)); \
    float2 _fb = __half22float2(*reinterpret_cast<__half2*>(&(r).y)); \
    ax += _fa.x; ay += _fa.y; az += _fb.x; aw += _fb.y; } while (0)

__device__ __forceinline__ float4 gather_sum2(const uint2* __restrict__ in2,
                                              int lo, int end, int side, int sub) {
    float ax = 0.f, ay = 0.f, az = 0.f, aw = 0.f;
    int j = lo;
    // peel to 4-aligned index; edge j belongs to side (j&1)
    while (j < end && (j & 3)) {
        if ((j & 1) == side) {
            uint2 r = in2[(((size_t)g_src[j]) << 4) + sub];
            ACC(r);
        }
        ++j;
    }
    const int4* __restrict__ s4 = reinterpret_cast<const int4*>(g_src);
    // 8 edges per trip: 2 shared int4 index loads, 4 gathers per half-warp in flight
    for (; j + 8 <= end; j += 8) {
        int4 a = s4[j >> 2];
        int4 b = s4[(j >> 2) + 1];
        int i0 = side ? a.y : a.x;
        int i1 = side ? a.w : a.z;
        int i2 = side ? b.y : b.x;
        int i3 = side ? b.w : b.z;
        uint2 r0 = in2[(((size_t)i0) << 4) + sub];
        uint2 r1 = in2[(((size_t)i1) << 4) + sub];
        uint2 r2 = in2[(((size_t)i2) << 4) + sub];
        uint2 r3 = in2[(((size_t)i3) << 4) + sub];
        ACC(r0); ACC(r1); ACC(r2); ACC(r3);
    }
    if (j + 4 <= end) {
        int4 a = s4[j >> 2];
        int i0 = side ? a.y : a.x;
        int i1 = side ? a.w : a.z;
        uint2 r0 = in2[(((size_t)i0) << 4) + sub];
        uint2 r1 = in2[(((size_t)i1) << 4) + sub];
        ACC(r0); ACC(r1);
        j += 4;
    }
    while (j < end) {
        if ((j & 1) == side) {
            uint2 r = in2[(((size_t)g_src[j]) << 4) + sub];
            ACC(r);
        }
        ++j;
    }
    ax += __shfl_xor_sync(0xffffffffu, ax, 16);
    ay += __shfl_xor_sync(0xffffffffu, ay, 16);
    az += __shfl_xor_sync(0xffffffffu, az, 16);
    aw += __shfl_xor_sync(0xffffffffu, aw, 16);
    return make_float4(ax, ay, az, aw);
}

// layers 0/1: s_out[v] = fp16( dinv[v]^2 * Σ s_in[src] )   [invariant: s = dinv ⊙ e]
__global__ void __launch_bounds__(256) k_prop(const __half2* __restrict__ in,
                                              __half2* __restrict__ out, int n) {
    int warp = (blockIdx.x * blockDim.x + threadIdx.x) >> 5;
    int lane = threadIdx.x & 31;
    if (warp >= n) return;
    int side = lane >> 4, sub = lane & 15;
    int lo = g_off[warp];
    float4 s = gather_sum2(reinterpret_cast<const uint2*>(in),
                           lo, lo + g_deg[warp], side, sub);
    if (side == 0) {
        float dv = g_dinv[warp];
        float d2 = dv * dv;                        // dinv^2 keeps the pre-scaled invariant
        __half2 oa = __float22half2_rn(make_float2(s.x * d2, s.y * d2));
        __half2 ob = __float22half2_rn(make_float2(s.z * d2, s.w * d2));
        uint2 o;
        o.x = *reinterpret_cast<unsigned*>(&oa);
        o.y = *reinterpret_cast<unsigned*>(&ob);
        reinterpret_cast<uint2*>(out)[(((size_t)warp) << 4) + sub] = o;
    }
}

// final: out = (emb0 + (s1+s2)*sqrt(deg) + dinv*Σ s2[src]) * 0.25; re-zero g_deg
__global__ void __launch_bounds__(256) k_prop_final(const float* __restrict__ emb0,
                                                    float* __restrict__ outp, int n) {
    int warp = (blockIdx.x * blockDim.x + threadIdx.x) >> 5;
    int lane = threadIdx.x & 31;
    if (warp >= n) return;
    int side = lane >> 4, sub = lane & 15;
    int lo = g_off[warp];
    int dg = g_deg[warp];
    float4 s = gather_sum2(reinterpret_cast<const uint2*>(g_s2),
                           lo, lo + dg, side, sub);

    if (side == 0) {
        float dv = g_dinv[warp];
        float sq = sqrtf((float)dg);               // e_k = s_k * sqrt(deg)
        size_t ro = (((size_t)warp) << 4) + sub;
        float4 e0 = reinterpret_cast<const float4*>(emb0)[ro];
        uint2 r1 = reinterpret_cast<const uint2*>(g_s1)[ro];
        uint2 r2 = reinterpret_cast<const uint2*>(g_s2)[ro];
        float2 a1a = __half22float2(*reinterpret_cast<__half2*>(&r1.x));
        float2 a1b = __half22float2(*reinterpret_cast<__half2*>(&r1.y));
        float2 a2a = __half22float2(*reinterpret_cast<__half2*>(&r2.x));
        float2 a2b = __half22float2(*reinterpret_cast<__half2*>(&r2.y));
        float4 r;
        r.x = (e0.x + (a1a.x + a2a.x) * sq + s.x * dv) * 0.25f;
        r.y = (e0.y + (a1a.y + a2a.y) * sq + s.y * dv) * 0.25f;
        r.z = (e0.z + (a1b.x + a2b.x) * sq + s.z * dv) * 0.25f;
        r.w = (e0.w + (a1b.y + a2b.y) * sq + s.w * dv) * 0.25f;
        reinterpret_cast<float4*>(outp)[ro] = r;
    }
    if (lane == 0) g_deg[warp] = 0;   // restore invariant for next graph replay
}

extern "C" void kernel_launch(void* const* d_in, const int* in_sizes, int n_in,
                              void* d_out, int out_size) {
    const int*   edges = (const int*)d_in[0];       // int32
    const float* emb   = (const float*)d_in[1];
    int E = in_sizes[0] / 2;
    int N = in_sizes[1] / D;

    const int* src = edges;
    const int* dst = edges + E;

    float* out0 = (float*)d_out;
    float* outp = out0 + (size_t)N * D;

    int tb = 256;
    int nbE = (E + tb - 1) / tb;
    int NB  = (N + SCAN_T - 1) / SCAN_T;

    k_count<<<nbE, tb>>>(dst, E);                   // launch 0
    k_scanA<<<NB, SCAN_T>>>(N);                     // launch 1 (scan + dinv)
    k_scanBC<<<NB, SCAN_T>>>(N, NB);                // launch 2
    k_fill<<<nbE, tb>>>(src, dst, E);               // launch 3

    int n4 = (N * D) / 4;
    k_init<<<(n4 + tb - 1) / tb, tb>>>((const float4*)emb, (float4*)out0, n4);  // 4

    __half2 *s0p, *s1p, *s2p;
    cudaGetSymbolAddress((void**)&s0p, g_s0);
    cudaGetSymbolAddress((void**)&s1p, g_s1);
    cudaGetSymbolAddress((void**)&s2p, g_s2);

    int pthreads = N * 32;                          // one warp per node
    int pblocks  = (pthreads + tb - 1) / tb;
    k_prop<<<pblocks, tb>>>(s0p, s1p, N);           // launch 5
    k_prop<<<pblocks, tb>>>(s1p, s2p, N);           // launch 6
    k_prop_final<<<pblocks, tb>>>(emb, outp, N);    // launch 7
}

// round 11
// speedup vs baseline: 1.2541x; 1.0079x over previous
#include <cuda_runtime.h>
#include <cuda_fp16.h>
#include <cstdint>

#define D 64
#define N_MAX 200000
#define E_MAX 4000000
#define SCAN_T 1024

// ---- scratch (static device globals; zero-initialized at module load) ----
__device__ int     g_deg[N_MAX];       // zeroed at load; re-zeroed by k_prop_final each call
__device__ int     g_off[N_MAX];
__device__ float   g_dinv[N_MAX];
__device__ __align__(16) int g_rank[E_MAX];     // per-edge rank within its dst bucket
__device__ __align__(16) int g_src[E_MAX];      // CSR adjacency: src only
__device__ __half2 g_s0[(size_t)N_MAX * 32];    // s0 = dinv ⊙ emb0   (fp16, pre-scaled)
__device__ __half2 g_s1[(size_t)N_MAX * 32];    // s1 = dinv ⊙ e1
__device__ __half2 g_s2[(size_t)N_MAX * 32];    // s2 = dinv ⊙ e2
__device__ int     g_bsum[256];

// ---------------- degree count + rank record, 4 edges/thread ----------------
__global__ void k_count(const int* __restrict__ dst, int E) {
    int i = (blockIdx.x * blockDim.x + threadIdx.x) * 4;
    if (i + 3 < E) {
        int4 d = *reinterpret_cast<const int4*>(dst + i);
        int4 r;
        r.x = atomicAdd(&g_deg[d.x], 1);
        r.y = atomicAdd(&g_deg[d.y], 1);
        r.z = atomicAdd(&g_deg[d.z], 1);
        r.w = atomicAdd(&g_deg[d.w], 1);
        *reinterpret_cast<int4*>(g_rank + i) = r;
    } else {
        for (; i < E; ++i) g_rank[i] = atomicAdd(&g_deg[dst[i]], 1);
    }
}

// ---------------- block-local exclusive scan + dinv fused ----------------
__global__ void k_scanA(int n) {
    __shared__ int s[SCAN_T];
    int t = threadIdx.x;
    int i = blockIdx.x * SCAN_T + t;
    int v = (i < n) ? g_deg[i] : 0;
    s[t] = v;
    __syncthreads();
    for (int d = 1; d < SCAN_T; d <<= 1) {
        int x = (t >= d) ? s[t - d] : 0;
        __syncthreads();
        s[t] += x;
        __syncthreads();
    }
    if (i < n) {
        g_off[i]  = s[t] - v;
        g_dinv[i] = (v > 0) ? rsqrtf((float)v) : 0.0f;
    }
    if (t == SCAN_T - 1) g_bsum[blockIdx.x] = s[t];
}

// ------- merged scanB+scanC + fused init (out0 = emb0, g_s0 = dinv ⊙ emb0) -------
__global__ void k_scanBC(int n, int nb, const float4* __restrict__ emb,
                         float4* __restrict__ o0, int n4) {
    __shared__ int s[256];
    int t = threadIdx.x;
    if (t < 256) s[t] = (t < nb) ? g_bsum[t] : 0;
    __syncthreads();
    for (int d = 1; d < 256; d <<= 1) {
        int x = (t < 256 && t >= d) ? s[t - d] : 0;
        __syncthreads();
        if (t < 256) s[t] += x;
        __syncthreads();
    }
    int excl = s[blockIdx.x] - g_bsum[blockIdx.x];
    int i = blockIdx.x * SCAN_T + t;
    if (i < n) g_off[i] += excl;

    // fused init: grid-stride over embedding rows (needs only dinv from scanA)
    int stride = gridDim.x * blockDim.x;
    for (int k = blockIdx.x * blockDim.x + t; k < n4; k += stride) {
        float4 v = emb[k];
        o0[k] = v;
        float dv = g_dinv[k >> 4];                 // 16 float4 per node row
        g_s0[2 * k]     = __float22half2_rn(make_float2(v.x * dv, v.y * dv));
        g_s0[2 * k + 1] = __float22half2_rn(make_float2(v.z * dv, v.w * dv));
    }
}

// ---------------- CSR fill: NO atomic — pos = off[dst] + rank, 4 edges/thread ----------------
__global__ void k_fill(const int* __restrict__ src,
                       const int* __restrict__ dst, int E) {
    int i = (blockIdx.x * blockDim.x + threadIdx.x) * 4;
    if (i + 3 < E) {
        int4 d = *reinterpret_cast<const int4*>(dst + i);
        int4 s = *reinterpret_cast<const int4*>(src + i);
        int4 r = *reinterpret_cast<const int4*>(g_rank + i);
        g_src[g_off[d.x] + r.x] = s.x;
        g_src[g_off[d.y] + r.y] = s.y;
        g_src[g_off[d.z] + r.z] = s.z;
        g_src[g_off[d.w] + r.w] = s.w;
    } else {
        for (; i < E; ++i) g_src[g_off[dst[i]] + g_rank[i]] = src[i];
    }
}

// ---------------- gather-sum: warp per node, half-warp per edge, plain adds ----------------
#define ACC(r) do { \
    float2 _fa = __half22float2(*reinterpret_cast<__half2*>(&(r).x)); \
    float2 _fb = __half22float2(*reinterpret_cast<__half2*>(&(r).y)); \
    ax += _fa.x; ay += _fa.y; az += _fb.x; aw += _fb.y; } while (0)

__device__ __forceinline__ float4 gather_sum2(const uint2* __restrict__ in2,
                                              int lo, int end, int side, int sub) {
    float ax = 0.f, ay = 0.f, az = 0.f, aw = 0.f;
    int j = lo;
    // peel to 4-aligned index; edge j belongs to side (j&1)
    while (j < end && (j & 3)) {
        if ((j & 1) == side) {
            uint2 r = in2[(((size_t)g_src[j]) << 4) + sub];
            ACC(r);
        }
        ++j;
    }
    const int4* __restrict__ s4 = reinterpret_cast<const int4*>(g_src);
    // 16 edges per trip: 4 shared int4 index loads, 8 gathers per half-warp in flight
    for (; j + 16 <= end; j += 16) {
        int4 a = s4[(j >> 2) + 0];
        int4 b = s4[(j >> 2) + 1];
        int4 c = s4[(j >> 2) + 2];
        int4 d = s4[(j >> 2) + 3];
        int i0 = side ? a.y : a.x;
        int i1 = side ? a.w : a.z;
        int i2 = side ? b.y : b.x;
        int i3 = side ? b.w : b.z;
        int i4 = side ? c.y : c.x;
        int i5 = side ? c.w : c.z;
        int i6 = side ? d.y : d.x;
        int i7 = side ? d.w : d.z;
        uint2 r0 = in2[(((size_t)i0) << 4) + sub];
        uint2 r1 = in2[(((size_t)i1) << 4) + sub];
        uint2 r2 = in2[(((size_t)i2) << 4) + sub];
        uint2 r3 = in2[(((size_t)i3) << 4) + sub];
        uint2 r4 = in2[(((size_t)i4) << 4) + sub];
        uint2 r5 = in2[(((size_t)i5) << 4) + sub];
        uint2 r6 = in2[(((size_t)i6) << 4) + sub];
        uint2 r7 = in2[(((size_t)i7) << 4) + sub];
        ACC(r0); ACC(r1); ACC(r2); ACC(r3);
        ACC(r4); ACC(r5); ACC(r6); ACC(r7);
    }
    for (; j + 4 <= end; j += 4) {
        int4 a = s4[j >> 2];
        int i0 = side ? a.y : a.x;
        int i1 = side ? a.w : a.z;
        uint2 r0 = in2[(((size_t)i0) << 4) + sub];
        uint2 r1 = in2[(((size_t)i1) << 4) + sub];
        ACC(r0); ACC(r1);
    }
    while (j < end) {
        if ((j & 1) == side) {
            uint2 r = in2[(((size_t)g_src[j]) << 4) + sub];
            ACC(r);
        }
        ++j;
    }
    ax += __shfl_xor_sync(0xffffffffu, ax, 16);
    ay += __shfl_xor_sync(0xffffffffu, ay, 16);
    az += __shfl_xor_sync(0xffffffffu, az, 16);
    aw += __shfl_xor_sync(0xffffffffu, aw, 16);
    return make_float4(ax, ay, az, aw);
}

// layers 0/1: s_out[v] = fp16( dinv[v]^2 * Σ s_in[src] )   [invariant: s = dinv ⊙ e]
__global__ void __launch_bounds__(256) k_prop(const __half2* __restrict__ in,
                                              __half2* __restrict__ out, int n) {
    int warp = (blockIdx.x * blockDim.x + threadIdx.x) >> 5;
    int lane = threadIdx.x & 31;
    if (warp >= n) return;
    int side = lane >> 4, sub = lane & 15;
    int lo = g_off[warp];
    float4 s = gather_sum2(reinterpret_cast<const uint2*>(in),
                           lo, lo + g_deg[warp], side, sub);
    if (side == 0) {
        float dv = g_dinv[warp];
        float d2 = dv * dv;
        __half2 oa = __float22half2_rn(make_float2(s.x * d2, s.y * d2));
        __half2 ob = __float22half2_rn(make_float2(s.z * d2, s.w * d2));
        uint2 o;
        o.x = *reinterpret_cast<unsigned*>(&oa);
        o.y = *reinterpret_cast<unsigned*>(&ob);
        reinterpret_cast<uint2*>(out)[(((size_t)warp) << 4) + sub] = o;
    }
}

// final: out = (emb0 + (s1+s2)*sqrt(deg) + dinv*Σ s2[src]) * 0.25; re-zero g_deg
__global__ void __launch_bounds__(256) k_prop_final(const float* __restrict__ emb0,
                                                    float* __restrict__ outp, int n) {
    int warp = (blockIdx.x * blockDim.x + threadIdx.x) >> 5;
    int lane = threadIdx.x & 31;
    if (warp >= n) return;
    int side = lane >> 4, sub = lane & 15;
    int lo = g_off[warp];
    int dg = g_deg[warp];
    float4 s = gather_sum2(reinterpret_cast<const uint2*>(g_s2),
                           lo, lo + dg, side, sub);

    if (side == 0) {
        float dv = g_dinv[warp];
        float sq = sqrtf((float)dg);               // e_k = s_k * sqrt(deg)
        size_t ro = (((size_t)warp) << 4) + sub;
        float4 e0 = reinterpret_cast<const float4*>(emb0)[ro];
        uint2 r1 = reinterpret_cast<const uint2*>(g_s1)[ro];
        uint2 r2 = reinterpret_cast<const uint2*>(g_s2)[ro];
        float2 a1a = __half22float2(*reinterpret_cast<__half2*>(&r1.x));
        float2 a1b = __half22float2(*reinterpret_cast<__half2*>(&r1.y));
        float2 a2a = __half22float2(*reinterpret_cast<__half2*>(&r2.x));
        float2 a2b = __half22float2(*reinterpret_cast<__half2*>(&r2.y));
        float4 r;
        r.x = (e0.x + (a1a.x + a2a.x) * sq + s.x * dv) * 0.25f;
        r.y = (e0.y + (a1a.y + a2a.y) * sq + s.y * dv) * 0.25f;
        r.z = (e0.z + (a1b.x + a2b.x) * sq + s.z * dv) * 0.25f;
        r.w = (e0.w + (a1b.y + a2b.y) * sq + s.w * dv) * 0.25f;
        reinterpret_cast<float4*>(outp)[ro] = r;
    }
    if (lane == 0) g_deg[warp] = 0;   // restore invariant for next graph replay
}

extern "C" void kernel_launch(void* const* d_in, const int* in_sizes, int n_in,
                              void* d_out, int out_size) {
    const int*   edges = (const int*)d_in[0];       // int32
    const float* emb   = (const float*)d_in[1];
    int E = in_sizes[0] / 2;
    int N = in_sizes[1] / D;

    const int* src = edges;
    const int* dst = edges + E;

    float* out0 = (float*)d_out;
    float* outp = out0 + (size_t)N * D;

    int tb = 256;
    int nbE4 = ((E + 3) / 4 + tb - 1) / tb;         // 4 edges per thread
    int NB   = (N + SCAN_T - 1) / SCAN_T;
    int n4   = (N * D) / 4;

    k_count<<<nbE4, tb>>>(dst, E);                                  // launch 0
    k_scanA<<<NB, SCAN_T>>>(N);                                     // launch 1
    k_scanBC<<<NB, SCAN_T>>>(N, NB, (const float4*)emb,
                             (float4*)out0, n4);                    // launch 2 (+init)
    k_fill<<<nbE4, tb>>>(src, dst, E);                              // launch 3

    __half2 *s0p, *s1p, *s2p;
    cudaGetSymbolAddress((void**)&s0p, g_s0);
    cudaGetSymbolAddress((void**)&s1p, g_s1);
    cudaGetSymbolAddress((void**)&s2p, g_s2);

    int pthreads = N * 32;                          // one warp per node
    int pblocks  = (pthreads + tb - 1) / tb;
    k_prop<<<pblocks, tb>>>(s0p, s1p, N);           // launch 4
    k_prop<<<pblocks, tb>>>(s1p, s2p, N);           // launch 5  <- ncu -s 5 lands here
    k_prop_final<<<pblocks, tb>>>(emb, outp, N);    // launch 6
}